// round 2
// baseline (speedup 1.0000x reference)
#include <cuda_runtime.h>
#include <cstdint>

#define NMAX 100352
#define D 512
#define H 16

// Scratch: h-buffer (post-GEMM node features) and agg-buffer (scatter target).
__device__ __align__(256) float g_h[NMAX * H];
__device__ __align__(256) float g_agg[NMAX * H];

// ---------------------------------------------------------------------------
// Kernel 1: h0 = X @ W1   (also zeros g_agg rows for this block's rows)
// Block: 128 threads. Each thread computes 2 rows x 16 cols.
// X staged through smem in 256-row x 16-k chunks (pad 17 -> conflict-free LDS).
// W1 chunk (16x16) staged per k-chunk; reads are warp-uniform broadcasts.
// ---------------------------------------------------------------------------
__global__ void __launch_bounds__(128) gemm1_kernel(
    const float* __restrict__ x, const float* __restrict__ W1, int N)
{
    __shared__ float xs[256 * 17];
    __shared__ float w1c[16 * 16];

    const int tid  = threadIdx.x;
    const int row0 = blockIdx.x * 256;

    float acc0[16], acc1[16];
#pragma unroll
    for (int c = 0; c < 16; c++) { acc0[c] = 0.f; acc1[c] = 0.f; }

    for (int k0 = 0; k0 < D; k0 += 16) {
        __syncthreads();
        // stage 256 rows x 16 k of X (1024 float4 loads, 8 per thread)
#pragma unroll
        for (int i = 0; i < 8; i++) {
            int idx = tid + i * 128;        // 0..1023
            int r   = idx >> 2;
            int q   = idx & 3;
            int grow = row0 + r;
            float4 v = make_float4(0.f, 0.f, 0.f, 0.f);
            if (grow < N)
                v = *(const float4*)(x + (size_t)grow * D + k0 + q * 4);
            float* dst = xs + r * 17 + q * 4;
            dst[0] = v.x; dst[1] = v.y; dst[2] = v.z; dst[3] = v.w;
        }
        // stage W1 chunk [16 k][16 c]
        w1c[tid]       = W1[k0 * 16 + tid];
        w1c[tid + 128] = W1[k0 * 16 + tid + 128];
        __syncthreads();

#pragma unroll
        for (int k = 0; k < 16; k++) {
            float xv0 = xs[tid * 17 + k];
            float xv1 = xs[(tid + 128) * 17 + k];
            float wv[16];
#pragma unroll
            for (int q = 0; q < 4; q++)
                *(float4*)(wv + 4 * q) = *(const float4*)(w1c + k * 16 + 4 * q);
#pragma unroll
            for (int c = 0; c < 16; c++) {
                acc0[c] += xv0 * wv[c];
                acc1[c] += xv1 * wv[c];
            }
        }
    }

    const float4 z4 = make_float4(0.f, 0.f, 0.f, 0.f);
    int r0 = row0 + tid;
    int r1 = r0 + 128;
    if (r0 < N) {
        float4* hp = (float4*)(g_h + (size_t)r0 * H);
        float4* ap = (float4*)(g_agg + (size_t)r0 * H);
#pragma unroll
        for (int q = 0; q < 4; q++) {
            hp[q] = make_float4(acc0[q*4+0], acc0[q*4+1], acc0[q*4+2], acc0[q*4+3]);
            ap[q] = z4;
        }
    }
    if (r1 < N) {
        float4* hp = (float4*)(g_h + (size_t)r1 * H);
        float4* ap = (float4*)(g_agg + (size_t)r1 * H);
#pragma unroll
        for (int q = 0; q < 4; q++) {
            hp[q] = make_float4(acc1[q*4+0], acc1[q*4+1], acc1[q*4+2], acc1[q*4+3]);
            ap[q] = z4;
        }
    }
}

// ---------------------------------------------------------------------------
// Kernel 2: edge scatter  agg[dst] += w * h[src]   (vector red, 4x f32 per op)
// h and agg are L2-resident (6.4 MB each). edge_index is int32 (JAX x64 off).
// ---------------------------------------------------------------------------
__device__ __forceinline__ void red4(float* p, float a, float b, float c, float d) {
    asm volatile("red.global.add.v4.f32 [%0], {%1, %2, %3, %4};"
                 :: "l"(p), "f"(a), "f"(b), "f"(c), "f"(d) : "memory");
}

__global__ void __launch_bounds__(256) scatter_kernel(
    const int* __restrict__ ei, const float* __restrict__ ew, int E)
{
    int e = blockIdx.x * blockDim.x + threadIdx.x;
    if (e >= E) return;
    int s = __ldg(ei + e);
    int d = __ldg(ei + (size_t)E + e);
    float w = __ldg(ew + e);

    const float4* h = (const float4*)(g_h + (size_t)s * H);
    float4 a = h[0], b = h[1], c = h[2], dd = h[3];
    float* o = g_agg + (size_t)d * H;
    red4(o + 0,  w * a.x,  w * a.y,  w * a.z,  w * a.w);
    red4(o + 4,  w * b.x,  w * b.y,  w * b.z,  w * b.w);
    red4(o + 8,  w * c.x,  w * c.y,  w * c.z,  w * c.w);
    red4(o + 12, w * dd.x, w * dd.y, w * dd.z, w * dd.w);
}

// ---------------------------------------------------------------------------
// Kernel 3: h1 = relu(agg + b1); h2pre = h1 @ W2  -> g_h;  re-zero g_agg row
// ---------------------------------------------------------------------------
__global__ void __launch_bounds__(256) layer2_kernel(
    const float* __restrict__ b1, const float* __restrict__ W2, int N)
{
    __shared__ float W2s[256];
    __shared__ float b1s[16];
    int tid = threadIdx.x;
    W2s[tid] = W2[tid];
    if (tid < 16) b1s[tid] = b1[tid];
    __syncthreads();

    int n = blockIdx.x * 256 + tid;
    if (n >= N) return;

    float h[16];
    const float4* ap = (const float4*)(g_agg + (size_t)n * H);
#pragma unroll
    for (int q = 0; q < 4; q++) *(float4*)(h + 4 * q) = ap[q];
#pragma unroll
    for (int k = 0; k < 16; k++) h[k] = fmaxf(h[k] + b1s[k], 0.f);

    float o[16];
#pragma unroll
    for (int c = 0; c < 16; c++) o[c] = 0.f;
#pragma unroll
    for (int k = 0; k < 16; k++) {
        float hv = h[k];
#pragma unroll
        for (int q = 0; q < 4; q++) {
            float4 w = *(const float4*)(W2s + k * 16 + q * 4);
            o[q*4+0] += hv * w.x; o[q*4+1] += hv * w.y;
            o[q*4+2] += hv * w.z; o[q*4+3] += hv * w.w;
        }
    }

    float4* hp = (float4*)(g_h + (size_t)n * H);
    float4* az = (float4*)(g_agg + (size_t)n * H);
    const float4 z4 = make_float4(0.f, 0.f, 0.f, 0.f);
#pragma unroll
    for (int q = 0; q < 4; q++) {
        hp[q] = make_float4(o[q*4+0], o[q*4+1], o[q*4+2], o[q*4+3]);
        az[q] = z4;
    }
}

// ---------------------------------------------------------------------------
// Kernel 4: out = log_softmax(agg + b2)
// ---------------------------------------------------------------------------
__global__ void __launch_bounds__(256) final_kernel(
    const float* __restrict__ b2, float* __restrict__ out, int N)
{
    __shared__ float b2s[16];
    int tid = threadIdx.x;
    if (tid < 16) b2s[tid] = b2[tid];
    __syncthreads();

    int n = blockIdx.x * 256 + tid;
    if (n >= N) return;

    float v[16];
    const float4* ap = (const float4*)(g_agg + (size_t)n * H);
#pragma unroll
    for (int q = 0; q < 4; q++) *(float4*)(v + 4 * q) = ap[q];
#pragma unroll
    for (int k = 0; k < 16; k++) v[k] += b2s[k];

    float m = v[0];
#pragma unroll
    for (int k = 1; k < 16; k++) m = fmaxf(m, v[k]);
    float s = 0.f;
#pragma unroll
    for (int k = 0; k < 16; k++) s += expf(v[k] - m);
    float l = logf(s) + m;

    float4* op = (float4*)(out + (size_t)n * H);
#pragma unroll
    for (int q = 0; q < 4; q++)
        op[q] = make_float4(v[q*4+0] - l, v[q*4+1] - l, v[q*4+2] - l, v[q*4+3] - l);
}

// ---------------------------------------------------------------------------
extern "C" void kernel_launch(void* const* d_in, const int* in_sizes, int n_in,
                              void* d_out, int out_size)
{
    const float* x  = (const float*)d_in[0];
    const int*   ei = (const int*)d_in[1];
    const float* ew = (const float*)d_in[2];
    const float* W1 = (const float*)d_in[3];
    const float* b1 = (const float*)d_in[4];
    const float* W2 = (const float*)d_in[5];
    const float* b2 = (const float*)d_in[6];
    float* out = (float*)d_out;

    int N = in_sizes[0] / D;      // 100000
    int E = in_sizes[2];          // 3200000

    int nblk = (N + 255) / 256;
    int eblk = (E + 255) / 256;

    // layer 1: GEMM (zeros agg) -> scatter
    gemm1_kernel<<<nblk, 128>>>(x, W1, N);
    scatter_kernel<<<eblk, 256>>>(ei, ew, E);
    // layer 2: relu + GEMM2 (re-zeros agg) -> scatter
    layer2_kernel<<<nblk, 256>>>(b1, W2, N);
    scatter_kernel<<<eblk, 256>>>(ei, ew, E);
    // log_softmax
    final_kernel<<<nblk, 256>>>(b2, out, N);
}

// round 3
// speedup vs baseline: 1.2594x; 1.2594x over previous
#include <cuda_runtime.h>
#include <cstdint>

#define NMAX 100352
#define D 512
#define H 16
#define GBLK 512   // rows per CTA in gemm1 (128 threads x 4 rows)

// Scratch: h-buffer (post-GEMM node features) and agg-buffer (scatter target).
__device__ __align__(256) float g_h[NMAX * H];
__device__ __align__(256) float g_agg[NMAX * H];

// ---------------------------------------------------------------------------
// f32x2 packed helpers (sm_103a: fma.rn.f32x2 only reachable via PTX)
// ---------------------------------------------------------------------------
__device__ __forceinline__ unsigned long long pk2(float lo, float hi) {
    unsigned long long r;
    asm("mov.b64 %0, {%1, %2};" : "=l"(r) : "f"(lo), "f"(hi));
    return r;
}
__device__ __forceinline__ void unpk2(unsigned long long v, float& lo, float& hi) {
    asm("mov.b64 {%0, %1}, %2;" : "=f"(lo), "=f"(hi) : "l"(v));
}
__device__ __forceinline__ void fma2(unsigned long long& acc,
                                     unsigned long long a, unsigned long long b) {
    asm("fma.rn.f32x2 %0, %1, %2, %0;" : "+l"(acc) : "l"(a), "l"(b));
}

// ---------------------------------------------------------------------------
// Kernel 1: h0 = X @ W1  (also zeros g_agg rows). 128 threads, 4 rows/thread,
// accumulators packed 2-rows-per-64b reg -> f32x2 FMA (half the FFMA instrs).
// X staged via smem (pad 17 -> conflict-free LDS); W chunk staged pre-packed
// as (w,w) pairs so inner-loop weight loads are single LDS.64 broadcasts.
// ---------------------------------------------------------------------------
__global__ void __launch_bounds__(128) gemm1_kernel(
    const float* __restrict__ x, const float* __restrict__ W1, int N)
{
    __shared__ float xs[GBLK * 17];
    __shared__ __align__(8) float w1p[16 * 16 * 2];   // packed (w,w) per [k][c]

    const int tid  = threadIdx.x;
    const int row0 = blockIdx.x * GBLK;

    unsigned long long acc0[16], acc1[16];   // pair0=(r, r+128), pair1=(r+256, r+384)
#pragma unroll
    for (int c = 0; c < 16; c++) { acc0[c] = 0ull; acc1[c] = 0ull; }

    for (int k0 = 0; k0 < D; k0 += 16) {
        __syncthreads();
        // stage 512 rows x 16 k of X: 2048 float4, 16 per thread
#pragma unroll
        for (int i = 0; i < 16; i++) {
            int idx = tid + i * 128;          // 0..2047
            int r   = idx >> 2;
            int q   = idx & 3;
            int grow = row0 + r;
            float4 v = make_float4(0.f, 0.f, 0.f, 0.f);
            if (grow < N)
                v = *(const float4*)(x + (size_t)grow * D + k0 + q * 4);
            float* dst = xs + r * 17 + q * 4;
            dst[0] = v.x; dst[1] = v.y; dst[2] = v.z; dst[3] = v.w;
        }
        // stage W chunk packed: 256 scalars -> 256 (w,w) float2
#pragma unroll
        for (int i = 0; i < 2; i++) {
            int j = tid + i * 128;
            float wv = W1[k0 * 16 + j];
            ((float2*)w1p)[j] = make_float2(wv, wv);
        }
        __syncthreads();

#pragma unroll
        for (int k = 0; k < 16; k++) {
            float a0 = xs[tid * 17 + k];
            float a1 = xs[(tid + 128) * 17 + k];
            float a2 = xs[(tid + 256) * 17 + k];
            float a3 = xs[(tid + 384) * 17 + k];
            unsigned long long p0 = pk2(a0, a1);
            unsigned long long p1 = pk2(a2, a3);
            const unsigned long long* wp = (const unsigned long long*)(w1p + k * 32);
#pragma unroll
            for (int c = 0; c < 16; c++) {
                unsigned long long w = wp[c];
                fma2(acc0[c], p0, w);
                fma2(acc1[c], p1, w);
            }
        }
    }

    // write h rows + zero agg rows
    const float4 z4 = make_float4(0.f, 0.f, 0.f, 0.f);
#pragma unroll
    for (int pr = 0; pr < 4; pr++) {
        int r = row0 + tid + pr * 128;
        if (r >= N) continue;
        float out[16];
#pragma unroll
        for (int c = 0; c < 16; c++) {
            float lo, hi;
            unpk2((pr < 2) ? acc0[c] : acc1[c], lo, hi);
            out[c] = (pr & 1) ? hi : lo;
        }
        float4* hp = (float4*)(g_h + (size_t)r * H);
        float4* ap = (float4*)(g_agg + (size_t)r * H);
#pragma unroll
        for (int q = 0; q < 4; q++) {
            hp[q] = make_float4(out[q*4+0], out[q*4+1], out[q*4+2], out[q*4+3]);
            ap[q] = z4;
        }
    }
}

// ---------------------------------------------------------------------------
// Kernel 2: edge scatter  agg[dst] += w * h[src]
// 4 lanes per edge, each lane owns one 16B quarter-row: one LDG.128 + one
// red.v4 per lane. Lanes of an edge share the 64B row -> sector merging;
// index loads are quad-redundant -> L1 broadcast merge.
// ---------------------------------------------------------------------------
__device__ __forceinline__ void red4(float* p, float a, float b, float c, float d) {
    asm volatile("red.global.add.v4.f32 [%0], {%1, %2, %3, %4};"
                 :: "l"(p), "f"(a), "f"(b), "f"(c), "f"(d) : "memory");
}

__global__ void __launch_bounds__(256) scatter_kernel(
    const int* __restrict__ ei, const float* __restrict__ ew, int E)
{
    int t = blockIdx.x * 256 + threadIdx.x;
    int e = t >> 2;
    if (e >= E) return;
    int q = t & 3;

    int   s = __ldg(ei + e);
    int   d = __ldg(ei + (size_t)E + e);
    float w = __ldg(ew + e);

    float4 v = *(const float4*)(g_h + (size_t)s * H + q * 4);
    red4(g_agg + (size_t)d * H + q * 4, w * v.x, w * v.y, w * v.z, w * v.w);
}

// ---------------------------------------------------------------------------
// Kernel 3: h1 = relu(agg + b1); h2pre = h1 @ W2  -> g_h;  re-zero g_agg row
// ---------------------------------------------------------------------------
__global__ void __launch_bounds__(256) layer2_kernel(
    const float* __restrict__ b1, const float* __restrict__ W2, int N)
{
    __shared__ float W2s[256];
    __shared__ float b1s[16];
    int tid = threadIdx.x;
    W2s[tid] = W2[tid];
    if (tid < 16) b1s[tid] = b1[tid];
    __syncthreads();

    int n = blockIdx.x * 256 + tid;
    if (n >= N) return;

    float h[16];
    const float4* ap = (const float4*)(g_agg + (size_t)n * H);
#pragma unroll
    for (int q = 0; q < 4; q++) *(float4*)(h + 4 * q) = ap[q];
#pragma unroll
    for (int k = 0; k < 16; k++) h[k] = fmaxf(h[k] + b1s[k], 0.f);

    float o[16];
#pragma unroll
    for (int c = 0; c < 16; c++) o[c] = 0.f;
#pragma unroll
    for (int k = 0; k < 16; k++) {
        float hv = h[k];
#pragma unroll
        for (int q = 0; q < 4; q++) {
            float4 w = *(const float4*)(W2s + k * 16 + q * 4);
            o[q*4+0] += hv * w.x; o[q*4+1] += hv * w.y;
            o[q*4+2] += hv * w.z; o[q*4+3] += hv * w.w;
        }
    }

    float4* hp = (float4*)(g_h + (size_t)n * H);
    float4* az = (float4*)(g_agg + (size_t)n * H);
    const float4 z4 = make_float4(0.f, 0.f, 0.f, 0.f);
#pragma unroll
    for (int q = 0; q < 4; q++) {
        hp[q] = make_float4(o[q*4+0], o[q*4+1], o[q*4+2], o[q*4+3]);
        az[q] = z4;
    }
}

// ---------------------------------------------------------------------------
// Kernel 4: out = log_softmax(agg + b2)
// ---------------------------------------------------------------------------
__global__ void __launch_bounds__(256) final_kernel(
    const float* __restrict__ b2, float* __restrict__ out, int N)
{
    __shared__ float b2s[16];
    int tid = threadIdx.x;
    if (tid < 16) b2s[tid] = b2[tid];
    __syncthreads();

    int n = blockIdx.x * 256 + tid;
    if (n >= N) return;

    float v[16];
    const float4* ap = (const float4*)(g_agg + (size_t)n * H);
#pragma unroll
    for (int q = 0; q < 4; q++) *(float4*)(v + 4 * q) = ap[q];
#pragma unroll
    for (int k = 0; k < 16; k++) v[k] += b2s[k];

    float m = v[0];
#pragma unroll
    for (int k = 1; k < 16; k++) m = fmaxf(m, v[k]);
    float s = 0.f;
#pragma unroll
    for (int k = 0; k < 16; k++) s += expf(v[k] - m);
    float l = logf(s) + m;

    float4* op = (float4*)(out + (size_t)n * H);
#pragma unroll
    for (int q = 0; q < 4; q++)
        op[q] = make_float4(v[q*4+0] - l, v[q*4+1] - l, v[q*4+2] - l, v[q*4+3] - l);
}

// ---------------------------------------------------------------------------
extern "C" void kernel_launch(void* const* d_in, const int* in_sizes, int n_in,
                              void* d_out, int out_size)
{
    const float* x  = (const float*)d_in[0];
    const int*   ei = (const int*)d_in[1];
    const float* ew = (const float*)d_in[2];
    const float* W1 = (const float*)d_in[3];
    const float* b1 = (const float*)d_in[4];
    const float* W2 = (const float*)d_in[5];
    const float* b2 = (const float*)d_in[6];
    float* out = (float*)d_out;

    int N = in_sizes[0] / D;      // 100000
    int E = in_sizes[2];          // 3200000

    int nblk  = (N + 255) / 256;
    int gblk  = (N + GBLK - 1) / GBLK;
    int eblk  = ((E * 4) + 255) / 256;   // 4 lanes per edge

    // layer 1: GEMM (zeros agg) -> scatter
    gemm1_kernel<<<gblk, 128>>>(x, W1, N);
    scatter_kernel<<<eblk, 256>>>(ei, ew, E);
    // layer 2: relu + GEMM2 (re-zeros agg) -> scatter
    layer2_kernel<<<nblk, 256>>>(b1, W2, N);
    scatter_kernel<<<eblk, 256>>>(ei, ew, E);
    // log_softmax
    final_kernel<<<nblk, 256>>>(b2, out, N);
}

// round 4
// speedup vs baseline: 1.5019x; 1.1925x over previous
#include <cuda_runtime.h>
#include <cstdint>

#define NMAX 100352
#define D 512
#define H 16
#define GBLK 256      // rows per CTA in gemm1 (128 threads x 2 rows)
#define CHUNK 32      // k-chunk (floats) = 128 B/row = 8 x 16B granules
#define NCHUNK (D / CHUNK)

__device__ __align__(256) float g_h[NMAX * H];
__device__ __align__(256) float g_agg[NMAX * H];

// ---------------------------------------------------------------------------
// f32x2 packed helpers
// ---------------------------------------------------------------------------
__device__ __forceinline__ unsigned long long pk2(float lo, float hi) {
    unsigned long long r;
    asm("mov.b64 %0, {%1, %2};" : "=l"(r) : "f"(lo), "f"(hi));
    return r;
}
__device__ __forceinline__ void unpk2(unsigned long long v, float& lo, float& hi) {
    asm("mov.b64 {%0, %1}, %2;" : "=f"(lo), "=f"(hi) : "l"(v));
}
__device__ __forceinline__ void fma2(unsigned long long& acc,
                                     unsigned long long a, unsigned long long b) {
    asm("fma.rn.f32x2 %0, %1, %2, %0;" : "+l"(acc) : "l"(a), "l"(b));
}
__device__ __forceinline__ unsigned int smem_u32(const void* p) {
    unsigned int a;
    asm("{ .reg .u64 t; cvta.to.shared.u64 t, %1; cvt.u32.u64 %0, t; }"
        : "=r"(a) : "l"(p));
    return a;
}
__device__ __forceinline__ void cp16(unsigned int dst, const void* src) {
    asm volatile("cp.async.cg.shared.global [%0], [%1], 16;" :: "r"(dst), "l"(src));
}

// ---------------------------------------------------------------------------
// Kernel 1: h0 = X @ W1 (also zeros g_agg rows).
// cp.async double-buffered staging (no register pressure, DRAM overlap),
// XOR-swizzled smem (conflict-free LDS.128), f32x2 packed accumulators.
// 128 threads, 2 rows/thread.
// ---------------------------------------------------------------------------
__global__ void __launch_bounds__(128) gemm1_kernel(
    const float* __restrict__ x, const float* __restrict__ W1, int N)
{
    __shared__ __align__(16) float4 xbuf[2][GBLK * 8];      // 2 x 32 KB
    __shared__ __align__(16) float  wbuf[CHUNK * 16 * 2];   // 4 KB packed (w,w)

    const int tid  = threadIdx.x;
    const int row0 = blockIdx.x * GBLK;
    const unsigned int xb_addr = smem_u32(xbuf);

    unsigned long long acc[16];   // pair = (row tid, row tid+128)
#pragma unroll
    for (int c = 0; c < 16; c++) acc[c] = 0ull;

    // ---- stage chunk `ch` into buffer `buf` via cp.async ----
    auto stage = [&](int ch, int buf) {
#pragma unroll
        for (int i = 0; i < 16; i++) {
            int g    = i * 128 + tid;          // 0..2047 granules
            int row  = g >> 3;
            int q    = g & 7;
            int grow = row0 + row;
            unsigned int dst = xb_addr +
                ((unsigned)(buf * GBLK * 8 + row * 8 + (q ^ (row & 7)))) * 16u;
            const float* src = x + (size_t)grow * D + ch * CHUNK + q * 4;
            if (grow < N) cp16(dst, src);      // predicated off on tail: stale smem,
        }                                      // garbage accs are store-guarded
        asm volatile("cp.async.commit_group;");
    };

    stage(0, 0);

    for (int ch = 0; ch < NCHUNK; ch++) {
        const int cur = ch & 1;
        if (ch + 1 < NCHUNK) stage(ch + 1, cur ^ 1);

        // stage W chunk packed (w,w): 512 floats, 4 per thread
        {
            float4 wv = *(const float4*)(W1 + ch * CHUNK * 16 + tid * 4);
            float2* wp = (float2*)wbuf;
            wp[tid * 4 + 0] = make_float2(wv.x, wv.x);
            wp[tid * 4 + 1] = make_float2(wv.y, wv.y);
            wp[tid * 4 + 2] = make_float2(wv.z, wv.z);
            wp[tid * 4 + 3] = make_float2(wv.w, wv.w);
        }

        if (ch + 1 < NCHUNK) asm volatile("cp.async.wait_group 1;");
        else                 asm volatile("cp.async.wait_group 0;");
        __syncthreads();

        const float4* xb = xbuf[cur];
#pragma unroll
        for (int kg = 0; kg < 8; kg++) {
            float4 a0 = xb[tid * 8 + (kg ^ (tid & 7))];
            float4 a1 = xb[(tid + 128) * 8 + (kg ^ (tid & 7))];
            float a0v[4] = {a0.x, a0.y, a0.z, a0.w};
            float a1v[4] = {a1.x, a1.y, a1.z, a1.w};
#pragma unroll
            for (int j = 0; j < 4; j++) {
                int k = kg * 4 + j;
                unsigned long long p = pk2(a0v[j], a1v[j]);
                const ulonglong2* wp = (const ulonglong2*)(wbuf + k * 32);
#pragma unroll
                for (int cp = 0; cp < 8; cp++) {
                    ulonglong2 w2 = wp[cp];
                    fma2(acc[cp * 2 + 0], p, w2.x);
                    fma2(acc[cp * 2 + 1], p, w2.y);
                }
            }
        }
        __syncthreads();   // protect wbuf + the buffer the next stage overwrites
    }

    // epilogue: write h rows + zero agg rows
    const float4 z4 = make_float4(0.f, 0.f, 0.f, 0.f);
#pragma unroll
    for (int pr = 0; pr < 2; pr++) {
        int r = row0 + tid + pr * 128;
        if (r >= N) continue;
        float out[16];
#pragma unroll
        for (int c = 0; c < 16; c++) {
            float lo, hi;
            unpk2(acc[c], lo, hi);
            out[c] = pr ? hi : lo;
        }
        float4* hp = (float4*)(g_h + (size_t)r * H);
        float4* ap = (float4*)(g_agg + (size_t)r * H);
#pragma unroll
        for (int q = 0; q < 4; q++) {
            hp[q] = make_float4(out[q*4+0], out[q*4+1], out[q*4+2], out[q*4+3]);
            ap[q] = z4;
        }
    }
}

// ---------------------------------------------------------------------------
// Kernel 2: edge scatter  agg[dst] += w * h[src]
// 4 lanes per edge: one LDG.128 + one red.v4 per lane.
// ---------------------------------------------------------------------------
__device__ __forceinline__ void red4(float* p, float a, float b, float c, float d) {
    asm volatile("red.global.add.v4.f32 [%0], {%1, %2, %3, %4};"
                 :: "l"(p), "f"(a), "f"(b), "f"(c), "f"(d) : "memory");
}

__global__ void __launch_bounds__(256) scatter_kernel(
    const int* __restrict__ ei, const float* __restrict__ ew, int E)
{
    int t = blockIdx.x * 256 + threadIdx.x;
    int e = t >> 2;
    if (e >= E) return;
    int q = t & 3;

    int   s = __ldg(ei + e);
    int   d = __ldg(ei + (size_t)E + e);
    float w = __ldg(ew + e);

    float4 v = *(const float4*)(g_h + (size_t)s * H + q * 4);
    red4(g_agg + (size_t)d * H + q * 4, w * v.x, w * v.y, w * v.z, w * v.w);
}

// ---------------------------------------------------------------------------
// Kernel 3: h1 = relu(agg + b1); h2pre = h1 @ W2 -> g_h; re-zero g_agg row
// ---------------------------------------------------------------------------
__global__ void __launch_bounds__(256) layer2_kernel(
    const float* __restrict__ b1, const float* __restrict__ W2, int N)
{
    __shared__ float W2s[256];
    __shared__ float b1s[16];
    int tid = threadIdx.x;
    W2s[tid] = W2[tid];
    if (tid < 16) b1s[tid] = b1[tid];
    __syncthreads();

    int n = blockIdx.x * 256 + tid;
    if (n >= N) return;

    float h[16];
    const float4* ap = (const float4*)(g_agg + (size_t)n * H);
#pragma unroll
    for (int q = 0; q < 4; q++) *(float4*)(h + 4 * q) = ap[q];
#pragma unroll
    for (int k = 0; k < 16; k++) h[k] = fmaxf(h[k] + b1s[k], 0.f);

    float o[16];
#pragma unroll
    for (int c = 0; c < 16; c++) o[c] = 0.f;
#pragma unroll
    for (int k = 0; k < 16; k++) {
        float hv = h[k];
#pragma unroll
        for (int q = 0; q < 4; q++) {
            float4 w = *(const float4*)(W2s + k * 16 + q * 4);
            o[q*4+0] += hv * w.x; o[q*4+1] += hv * w.y;
            o[q*4+2] += hv * w.z; o[q*4+3] += hv * w.w;
        }
    }

    float4* hp = (float4*)(g_h + (size_t)n * H);
    float4* az = (float4*)(g_agg + (size_t)n * H);
    const float4 z4 = make_float4(0.f, 0.f, 0.f, 0.f);
#pragma unroll
    for (int q = 0; q < 4; q++) {
        hp[q] = make_float4(o[q*4+0], o[q*4+1], o[q*4+2], o[q*4+3]);
        az[q] = z4;
    }
}

// ---------------------------------------------------------------------------
// Kernel 4: out = log_softmax(agg + b2)
// ---------------------------------------------------------------------------
__global__ void __launch_bounds__(256) final_kernel(
    const float* __restrict__ b2, float* __restrict__ out, int N)
{
    __shared__ float b2s[16];
    int tid = threadIdx.x;
    if (tid < 16) b2s[tid] = b2[tid];
    __syncthreads();

    int n = blockIdx.x * 256 + tid;
    if (n >= N) return;

    float v[16];
    const float4* ap = (const float4*)(g_agg + (size_t)n * H);
#pragma unroll
    for (int q = 0; q < 4; q++) *(float4*)(v + 4 * q) = ap[q];
#pragma unroll
    for (int k = 0; k < 16; k++) v[k] += b2s[k];

    float m = v[0];
#pragma unroll
    for (int k = 1; k < 16; k++) m = fmaxf(m, v[k]);
    float s = 0.f;
#pragma unroll
    for (int k = 0; k < 16; k++) s += expf(v[k] - m);
    float l = logf(s) + m;

    float4* op = (float4*)(out + (size_t)n * H);
#pragma unroll
    for (int q = 0; q < 4; q++)
        op[q] = make_float4(v[q*4+0] - l, v[q*4+1] - l, v[q*4+2] - l, v[q*4+3] - l);
}

// ---------------------------------------------------------------------------
extern "C" void kernel_launch(void* const* d_in, const int* in_sizes, int n_in,
                              void* d_out, int out_size)
{
    const float* x  = (const float*)d_in[0];
    const int*   ei = (const int*)d_in[1];
    const float* ew = (const float*)d_in[2];
    const float* W1 = (const float*)d_in[3];
    const float* b1 = (const float*)d_in[4];
    const float* W2 = (const float*)d_in[5];
    const float* b2 = (const float*)d_in[6];
    float* out = (float*)d_out;

    int N = in_sizes[0] / D;      // 100000
    int E = in_sizes[2];          // 3200000

    int nblk = (N + 255) / 256;
    int gblk = (N + GBLK - 1) / GBLK;
    int eblk = ((E * 4) + 255) / 256;   // 4 lanes per edge

    gemm1_kernel<<<gblk, 128>>>(x, W1, N);
    scatter_kernel<<<eblk, 256>>>(ei, ew, E);
    layer2_kernel<<<nblk, 256>>>(b1, W2, N);
    scatter_kernel<<<eblk, 256>>>(ei, ew, E);
    final_kernel<<<nblk, 256>>>(b2, out, N);
}